// round 5
// baseline (speedup 1.0000x reference)
#include <cuda_runtime.h>
#include <cuda_bf16.h>
#include <cstdint>

// Problem constants (fixed by the dataset)
#define BB 512      // batch
#define TT 512      // timesteps
#define II 128      // sensory inputs
#define UU 64       // LTC units
#define OO 15       // outputs
#define NUNF 4      // ode unfolds
#define LTC_EPS 1e-8f

#define SYN_REG 56              // recurrent synapses kept in registers per thread
#define SYN_SMEM (UU - SYN_REG) // remaining synapses read from a shared table (8)

// ---------------- device scratch (allocation-free rule: __device__ globals) ---------
__device__ float4 g_sparam[II * UU];     // sensory per-synapse {a, b, ce, c}
__device__ float4 g_rparam[UU * UU];     // recurrent per-synapse {a, b, ce, c}
__device__ float  g_sKn[UU], g_sKd[UU];  // sensory constant sums
__device__ float  g_cmt[UU], g_numbase[UU], g_denbase[UU];
__device__ float2 g_wns[BB * TT * UU];   // (w_num_s, w_den_s) per (b,t,u)  ~134MB

// ---------------- helpers ------------------------------------------------------------
__device__ __forceinline__ float tanh_fast(float x) {
    float y;
    asm("tanh.approx.f32 %0, %1;" : "=f"(y) : "f"(x));
    return y;
}
__device__ __forceinline__ float softplus_f(float x) {
    return log1pf(expf(x));
}

// ---------------- kernel 0a: fold parameters (one thread per synapse) -----------------
// sigmoid(z) = 0.5*tanh(z/2) + 0.5
// sensory arg = 0.5*sigma*(x*iw + ib - mu)   -> a = 0.5*sigma*iw, b = 0.5*sigma*(ib - mu)
// s_act = sp(w)*sigmoid = c + c*th, c = 0.5*sp(w); num term uses ce = c*erev
// NOTE: erev is exactly +-1, so c == fabsf(ce).
__global__ void fold_params_kernel(
    const float* __restrict__ iw, const float* __restrict__ ib,
    const float* __restrict__ sw, const float* __restrict__ smu,
    const float* __restrict__ ssig, const float* __restrict__ serev,
    const float* __restrict__ w, const float* __restrict__ mu,
    const float* __restrict__ sig, const float* __restrict__ erev)
{
    int idx = blockIdx.x * blockDim.x + threadIdx.x;
    if (idx < II * UU) {
        int i = idx / UU;
        float c  = 0.5f * softplus_f(sw[idx]);
        float ce = c * serev[idx];
        float a  = 0.5f * ssig[idx] * iw[i];
        float b  = 0.5f * ssig[idx] * (ib[i] - smu[idx]);
        g_sparam[idx] = make_float4(a, b, ce, c);
    }
    int r = idx - II * UU;
    if (r >= 0 && r < UU * UU) {
        float c  = 0.5f * softplus_f(w[r]);
        float ce = c * erev[r];
        float a  = 0.5f * sig[r];
        float b  = -0.5f * sig[r] * mu[r];
        g_rparam[r] = make_float4(a, b, ce, c);
    }
}

// ---------------- kernel 0b: per-neuron constant sums ---------------------------------
__global__ void fold_neuron_kernel(
    const float* __restrict__ gleak, const float* __restrict__ vleak,
    const float* __restrict__ cm)
{
    int u = threadIdx.x;
    if (u >= UU) return;

    float kn = 0.f, kd = 0.f;
#pragma unroll 8
    for (int i = 0; i < II; i++) {
        float4 p = g_sparam[i * UU + u];
        kn += p.z; kd += p.w;
    }
    g_sKn[u] = kn;
    g_sKd[u] = kd;

    kn = 0.f; kd = 0.f;
#pragma unroll 8
    for (int j = 0; j < UU; j++) {
        float4 p = g_rparam[j * UU + u];
        kn += p.z; kd += p.w;
    }
    float gp  = softplus_f(gleak[u]);
    float cmt = (float)NUNF * softplus_f(cm[u]);   // sp(cm) / (1/UNFOLDS)
    g_cmt[u]     = cmt;
    g_numbase[u] = gp * vleak[u] + kn;
    g_denbase[u] = cmt + gp + kd + LTC_EPS;
}

// ---------------- kernel 1: sensory synapse sums over all (b,t) ----------------------
// Barrier-free, no smem. 512 threads: u = tid>>3, ig = tid&7 (8 groups of 16 inputs).
// Two rows per iteration -> 32 independent tanh between shuffle tails.
#define ROWS_PER_BLOCK 128
__global__ __launch_bounds__(512, 1) void sensory_kernel(const float* __restrict__ x)
{
    const int tid = threadIdx.x;
    const int u  = tid >> 3;
    const int ig = tid & 7;

    float pa[16], pb[16], pce[16];
#pragma unroll
    for (int ii = 0; ii < 16; ii++) {
        float4 p = g_sparam[(ig * 16 + ii) * UU + u];
        pa[ii] = p.x; pb[ii] = p.y; pce[ii] = p.z;
    }
    const float kn = g_sKn[u];
    const float kd = g_sKd[u];

    const size_t base_row = (size_t)blockIdx.x * ROWS_PER_BLOCK;
    const float4* __restrict__ xr = (const float4*)x + base_row * (II / 4) + ig * 4;

    for (int r = 0; r < ROWS_PER_BLOCK; r += 2) {
        float4 x0[4], x1[4];
#pragma unroll
        for (int q = 0; q < 4; q++) {
            x0[q] = xr[(size_t)r * (II / 4) + q];
            x1[q] = xr[(size_t)(r + 1) * (II / 4) + q];
        }

        float pn0 = 0.f, pd0 = 0.f, pn1 = 0.f, pd1 = 0.f;
#pragma unroll
        for (int q = 0; q < 4; q++) {
            const int s = q * 4;
            const float xv0[4] = {x0[q].x, x0[q].y, x0[q].z, x0[q].w};
            const float xv1[4] = {x1[q].x, x1[q].y, x1[q].z, x1[q].w};
#pragma unroll
            for (int e = 0; e < 4; e++) {
                float t0 = tanh_fast(fmaf(pa[s + e], xv0[e], pb[s + e]));
                float t1 = tanh_fast(fmaf(pa[s + e], xv1[e], pb[s + e]));
                float ce = pce[s + e];
                float c  = fabsf(ce);
                pn0 = fmaf(ce, t0, pn0);  pd0 = fmaf(c, t0, pd0);
                pn1 = fmaf(ce, t1, pn1);  pd1 = fmaf(c, t1, pd1);
            }
        }
#pragma unroll
        for (int o = 1; o <= 4; o <<= 1) {
            pn0 += __shfl_xor_sync(0xffffffffu, pn0, o);
            pn1 += __shfl_xor_sync(0xffffffffu, pn1, o);
            pd0 += __shfl_xor_sync(0xffffffffu, pd0, o);
            pd1 += __shfl_xor_sync(0xffffffffu, pd1, o);
        }
        if (ig == 0) {
            __stcg(&g_wns[(base_row + r) * UU + u],     make_float2(pn0 + kn, pd0 + kd));
            __stcg(&g_wns[(base_row + r + 1) * UU + u], make_float2(pn1 + kn, pd1 + kd));
        }
    }
}

// ---------------- kernel 2: sequential scan + LayerNorm + FC head --------------------
// grid=128, block=128. sub = tid>>6 (0/1), u = tid&63. Each sub owns 2 batches;
// thread u owns unit u FULLY for both batches (no shfl, local division).
// Per barrier round: one unfold of BOTH batches -> 128 independent tanh per thread
// between barriers; batch A's divide/store tail overlaps batch B's MUFU burst.
// Params: 56 synapses in registers (168 regs) + 8 from a block-shared smem table.
__global__ __launch_bounds__(128) void scan_kernel(
    const float* __restrict__ outw, const float* __restrict__ outb,
    const float* __restrict__ lnw,  const float* __restrict__ lnb,
    const float* __restrict__ fcw,  const float* __restrict__ fcb,
    float* __restrict__ out)
{
    __shared__ float4 ptab[SYN_SMEM][UU];      // tail params {a,b,ce,c}, 8KB
    __shared__ float4 vsm4[4][2][UU / 4];      // v per (local batch, buffer)
    __shared__ float  hbuf[4][UU];
    __shared__ float  stats[4][2];

    const int tid = threadIdx.x;
    const int sub = tid >> 6;       // 0,1
    const int u   = tid & 63;       // unit owned
    const int b0  = blockIdx.x * 4; // batches b0..b0+3; sub handles b0+2*sub{,+1}

    // cooperative copy of tail params into smem: SYN_SMEM*UU = 512 float4
    {
        const float4* src = g_rparam + SYN_REG * UU;  // rows SYN_REG..63
#pragma unroll
        for (int q = 0; q < (SYN_SMEM * UU) / 128; q++)
            ((float4*)ptab)[q * 128 + tid] = src[q * 128 + tid];
    }

    float pa[SYN_REG], pb[SYN_REG], pce[SYN_REG];
#pragma unroll
    for (int j = 0; j < SYN_REG; j++) {
        float4 p = g_rparam[j * UU + u];
        pa[j] = p.x; pb[j] = p.y; pce[j] = p.z;
    }
    const float cmtu = g_cmt[u];
    const float nb   = g_numbase[u];
    const float db   = g_denbase[u];

    // init v buffers
    if (sub == 0) {
#pragma unroll
        for (int lb = 0; lb < 4; lb++)
            ((float*)vsm4[lb][0])[u] = 0.f;
    }
    float vA = 0.f, vB = 0.f;
    __syncthreads();

    const int lbA = sub * 2, lbB = sub * 2 + 1;
    const float2* __restrict__ wnsA = g_wns + (size_t)(b0 + lbA) * TT * UU;
    const float2* __restrict__ wnsB = g_wns + (size_t)(b0 + lbB) * TT * UU;

    float2 wndA = __ldcg(&wnsA[u]);
    float2 wndB = __ldcg(&wnsB[u]);

    for (int t = 0; t < TT; t++) {
        float2 wndA_n, wndB_n;
        if (t + 1 < TT) {
            wndA_n = __ldcg(&wnsA[(t + 1) * UU + u]);
            wndB_n = __ldcg(&wnsB[(t + 1) * UU + u]);
        } else {
            wndA_n = make_float2(0.f, 0.f);
            wndB_n = make_float2(0.f, 0.f);
        }
#pragma unroll
        for (int k = 0; k < NUNF; k++) {
            const int cur = k & 1, nxt = cur ^ 1;
            const float4* vrA = vsm4[lbA][cur];
            const float4* vrB = vsm4[lbB][cur];

            float pnA = 0.f, pdA = 0.f, pnB = 0.f, pdB = 0.f;
            // register-resident synapses 0..SYN_REG-1 (14 float4 groups)
#pragma unroll
            for (int q = 0; q < SYN_REG / 4; q++) {
                float4 a4 = vrA[q];
                float4 b4 = vrB[q];
                const int s = q * 4;
                const float va[4] = {a4.x, a4.y, a4.z, a4.w};
                const float vb[4] = {b4.x, b4.y, b4.z, b4.w};
#pragma unroll
                for (int e = 0; e < 4; e++) {
                    float tA = tanh_fast(fmaf(pa[s + e], va[e], pb[s + e]));
                    float tB = tanh_fast(fmaf(pa[s + e], vb[e], pb[s + e]));
                    float ce = pce[s + e];
                    float c  = fabsf(ce);
                    pnA = fmaf(ce, tA, pnA);  pdA = fmaf(c, tA, pdA);
                    pnB = fmaf(ce, tB, pnB);  pdB = fmaf(c, tB, pdB);
                }
            }
            // smem-resident synapses SYN_REG..63 (2 float4 groups)
#pragma unroll
            for (int q = SYN_REG / 4; q < UU / 4; q++) {
                float4 a4 = vrA[q];
                float4 b4 = vrB[q];
                const float va[4] = {a4.x, a4.y, a4.z, a4.w};
                const float vb[4] = {b4.x, b4.y, b4.z, b4.w};
#pragma unroll
                for (int e = 0; e < 4; e++) {
                    float4 pp = ptab[q * 4 + e - SYN_REG][u];
                    float tA = tanh_fast(fmaf(pp.x, va[e], pp.y));
                    float tB = tanh_fast(fmaf(pp.x, vb[e], pp.y));
                    pnA = fmaf(pp.z, tA, pnA);  pdA = fmaf(pp.w, tA, pdA);
                    pnB = fmaf(pp.z, tB, pnB);  pdB = fmaf(pp.w, tB, pdB);
                }
            }
            float numA = fmaf(cmtu, vA, nb) + wndA.x + pnA;
            float denA = db + wndA.y + pdA;
            vA = __fdividef(numA, denA);
            ((float*)vsm4[lbA][nxt])[u] = vA;

            float numB = fmaf(cmtu, vB, nb) + wndB.x + pnB;
            float denB = db + wndB.y + pdB;
            vB = __fdividef(numB, denB);
            ((float*)vsm4[lbB][nxt])[u] = vB;

            __syncthreads();
        }
        wndA = wndA_n;
        wndB = wndB_n;
    }

    // ----- head: per local batch: h = v*ow + ob; LayerNorm(eps=1e-5); FC -----
    {
        float ow = outw[u], ob = outb[u];
        hbuf[lbA][u] = fmaf(vA, ow, ob);
        hbuf[lbB][u] = fmaf(vB, ow, ob);
    }
    __syncthreads();
    {
        const int wid  = tid >> 5;   // warp w reduces batch w
        const int lane = tid & 31;
        float h0 = hbuf[wid][lane], h1 = hbuf[wid][lane + 32];
        float a = h0 + h1;
        float q = h0 * h0 + h1 * h1;
#pragma unroll
        for (int o = 16; o > 0; o >>= 1) {
            a += __shfl_down_sync(0xffffffffu, a, o);
            q += __shfl_down_sync(0xffffffffu, q, o);
        }
        if (lane == 0) {
            float mean = a * (1.0f / UU);
            float var  = q * (1.0f / UU) - mean * mean;
            stats[wid][0] = mean;
            stats[wid][1] = rsqrtf(var + 1e-5f);
        }
        __syncwarp();
        float mean = stats[wid][0], rstd = stats[wid][1];
        hbuf[wid][lane]      = fmaf((h0 - mean) * rstd, lnw[lane],      lnb[lane]);
        hbuf[wid][lane + 32] = fmaf((h1 - mean) * rstd, lnw[lane + 32], lnb[lane + 32]);
        __syncwarp();
        if (lane < OO) {
            float acc = fcb[lane];
#pragma unroll
            for (int uu = 0; uu < UU; uu++)
                acc = fmaf(hbuf[wid][uu], fcw[lane * UU + uu], acc);
            out[(b0 + wid) * OO + lane] = acc;
        }
    }
}

// ---------------- launch --------------------------------------------------------------
extern "C" void kernel_launch(void* const* d_in, const int* in_sizes, int n_in,
                              void* d_out, int out_size)
{
    const float* x     = (const float*)d_in[0];
    const float* iw    = (const float*)d_in[1];
    const float* ibv   = (const float*)d_in[2];
    const float* sw    = (const float*)d_in[3];
    const float* smu   = (const float*)d_in[4];
    const float* ssig  = (const float*)d_in[5];
    const float* serev = (const float*)d_in[6];
    const float* w     = (const float*)d_in[7];
    const float* mu    = (const float*)d_in[8];
    const float* sig   = (const float*)d_in[9];
    const float* erev  = (const float*)d_in[10];
    const float* gleak = (const float*)d_in[11];
    const float* vleak = (const float*)d_in[12];
    const float* cm    = (const float*)d_in[13];
    const float* outw  = (const float*)d_in[14];
    const float* outb  = (const float*)d_in[15];
    const float* lnw   = (const float*)d_in[16];
    const float* lnb   = (const float*)d_in[17];
    const float* fcw   = (const float*)d_in[18];
    const float* fcb   = (const float*)d_in[19];
    float* out = (float*)d_out;

    const int n_syn = II * UU + UU * UU;           // 12288
    fold_params_kernel<<<(n_syn + 255) / 256, 256>>>(iw, ibv, sw, smu, ssig, serev,
                                                     w, mu, sig, erev);
    fold_neuron_kernel<<<1, 64>>>(gleak, vleak, cm);

    int nblocks = (BB * TT) / ROWS_PER_BLOCK;      // 2048
    sensory_kernel<<<nblocks, 512>>>(x);

    scan_kernel<<<BB / 4, 128>>>(outw, outb, lnw, lnb, fcw, fcb, out);
}

// round 6
// speedup vs baseline: 2.0542x; 2.0542x over previous
#include <cuda_runtime.h>
#include <cuda_bf16.h>
#include <cstdint>

// Problem constants (fixed by the dataset)
#define BB 512      // batch
#define TT 512      // timesteps
#define II 128      // sensory inputs
#define UU 64       // LTC units
#define OO 15       // outputs
#define NUNF 4      // ode unfolds
#define LTC_EPS 1e-8f

#define SYN_REG 32              // recurrent synapses in registers per thread
#define SYN_SMEM (UU - SYN_REG) // recurrent synapses read from block smem (32)

// ---------------- device scratch (allocation-free rule: __device__ globals) ---------
__device__ float4 g_sparam[II * UU];     // sensory per-synapse {a, b, ce, c}
__device__ float4 g_rparam[UU * UU];     // recurrent per-synapse {a, b, ce, c}
__device__ float  g_sKn[UU], g_sKd[UU];  // sensory constant sums
__device__ float  g_cmt[UU], g_numbase[UU], g_denbase[UU];
__device__ float2 g_wns[BB * TT * UU];   // (w_num_s, w_den_s) per (b,t,u)  ~134MB

// ---------------- helpers ------------------------------------------------------------
__device__ __forceinline__ float tanh_fast(float x) {
    float y;
    asm("tanh.approx.f32 %0, %1;" : "=f"(y) : "f"(x));
    return y;
}
__device__ __forceinline__ float softplus_f(float x) {
    return log1pf(expf(x));
}

// ---------------- kernel 0a: fold parameters (one thread per synapse) -----------------
// sigmoid(z) = 0.5*tanh(z/2) + 0.5
// sensory arg = 0.5*sigma*(x*iw + ib - mu)   -> a = 0.5*sigma*iw, b = 0.5*sigma*(ib - mu)
// s_act = sp(w)*sigmoid = c + c*th, c = 0.5*sp(w); num term uses ce = c*erev
// NOTE: erev is exactly +-1, so c == fabsf(ce).
__global__ void fold_params_kernel(
    const float* __restrict__ iw, const float* __restrict__ ib,
    const float* __restrict__ sw, const float* __restrict__ smu,
    const float* __restrict__ ssig, const float* __restrict__ serev,
    const float* __restrict__ w, const float* __restrict__ mu,
    const float* __restrict__ sig, const float* __restrict__ erev)
{
    int idx = blockIdx.x * blockDim.x + threadIdx.x;
    if (idx < II * UU) {
        int i = idx / UU;
        float c  = 0.5f * softplus_f(sw[idx]);
        float ce = c * serev[idx];
        float a  = 0.5f * ssig[idx] * iw[i];
        float b  = 0.5f * ssig[idx] * (ib[i] - smu[idx]);
        g_sparam[idx] = make_float4(a, b, ce, c);
    }
    int r = idx - II * UU;
    if (r >= 0 && r < UU * UU) {
        float c  = 0.5f * softplus_f(w[r]);
        float ce = c * erev[r];
        float a  = 0.5f * sig[r];
        float b  = -0.5f * sig[r] * mu[r];
        g_rparam[r] = make_float4(a, b, ce, c);
    }
}

// ---------------- kernel 0b: per-neuron constant sums ---------------------------------
__global__ void fold_neuron_kernel(
    const float* __restrict__ gleak, const float* __restrict__ vleak,
    const float* __restrict__ cm)
{
    int u = threadIdx.x;
    if (u >= UU) return;

    float kn = 0.f, kd = 0.f;
#pragma unroll 8
    for (int i = 0; i < II; i++) {
        float4 p = g_sparam[i * UU + u];
        kn += p.z; kd += p.w;
    }
    g_sKn[u] = kn;
    g_sKd[u] = kd;

    kn = 0.f; kd = 0.f;
#pragma unroll 8
    for (int j = 0; j < UU; j++) {
        float4 p = g_rparam[j * UU + u];
        kn += p.z; kd += p.w;
    }
    float gp  = softplus_f(gleak[u]);
    float cmt = (float)NUNF * softplus_f(cm[u]);   // sp(cm) / (1/UNFOLDS)
    g_cmt[u]     = cmt;
    g_numbase[u] = gp * vleak[u] + kn;
    g_denbase[u] = cmt + gp + kd + LTC_EPS;
}

// ---------------- kernel 1: sensory synapse sums over all (b,t) ----------------------
// Barrier-free, no smem. 512 threads: u = tid>>3, ig = tid&7 (8 groups of 16 inputs).
// Two rows per iteration -> 32 independent tanh between shuffle tails.
#define ROWS_PER_BLOCK 128
__global__ __launch_bounds__(512, 1) void sensory_kernel(const float* __restrict__ x)
{
    const int tid = threadIdx.x;
    const int u  = tid >> 3;
    const int ig = tid & 7;

    float pa[16], pb[16], pce[16];
#pragma unroll
    for (int ii = 0; ii < 16; ii++) {
        float4 p = g_sparam[(ig * 16 + ii) * UU + u];
        pa[ii] = p.x; pb[ii] = p.y; pce[ii] = p.z;
    }
    const float kn = g_sKn[u];
    const float kd = g_sKd[u];

    const size_t base_row = (size_t)blockIdx.x * ROWS_PER_BLOCK;
    const float4* __restrict__ xr = (const float4*)x + base_row * (II / 4) + ig * 4;

    for (int r = 0; r < ROWS_PER_BLOCK; r += 2) {
        float4 x0[4], x1[4];
#pragma unroll
        for (int q = 0; q < 4; q++) {
            x0[q] = xr[(size_t)r * (II / 4) + q];
            x1[q] = xr[(size_t)(r + 1) * (II / 4) + q];
        }

        float pn0 = 0.f, pd0 = 0.f, pn1 = 0.f, pd1 = 0.f;
#pragma unroll
        for (int q = 0; q < 4; q++) {
            const int s = q * 4;
            const float xv0[4] = {x0[q].x, x0[q].y, x0[q].z, x0[q].w};
            const float xv1[4] = {x1[q].x, x1[q].y, x1[q].z, x1[q].w};
#pragma unroll
            for (int e = 0; e < 4; e++) {
                float t0 = tanh_fast(fmaf(pa[s + e], xv0[e], pb[s + e]));
                float t1 = tanh_fast(fmaf(pa[s + e], xv1[e], pb[s + e]));
                float ce = pce[s + e];
                float c  = fabsf(ce);
                pn0 = fmaf(ce, t0, pn0);  pd0 = fmaf(c, t0, pd0);
                pn1 = fmaf(ce, t1, pn1);  pd1 = fmaf(c, t1, pd1);
            }
        }
#pragma unroll
        for (int o = 1; o <= 4; o <<= 1) {
            pn0 += __shfl_xor_sync(0xffffffffu, pn0, o);
            pn1 += __shfl_xor_sync(0xffffffffu, pn1, o);
            pd0 += __shfl_xor_sync(0xffffffffu, pd0, o);
            pd1 += __shfl_xor_sync(0xffffffffu, pd1, o);
        }
        if (ig == 0) {
            __stcg(&g_wns[(base_row + r) * UU + u],     make_float2(pn0 + kn, pd0 + kd));
            __stcg(&g_wns[(base_row + r + 1) * UU + u], make_float2(pn1 + kn, pd1 + kd));
        }
    }
}

// ---------------- kernel 2: sequential scan + LayerNorm + FC head --------------------
// grid=256, block=128. sub = tid>>6 (one batch per sub), u = tid&63.
// Thread u owns unit u FULLY (no shfl, local division). Params: 32 synapses in
// registers (96 regs) + 32 in a block-shared smem table (24.5KB, conflict-free:
// lane index == u). ~2 blocks/SM -> 2 warps/SMSP from independent barrier domains
// hide each other's per-unfold tails.
__global__ __launch_bounds__(128, 2) void scan_kernel(
    const float* __restrict__ outw, const float* __restrict__ outb,
    const float* __restrict__ lnw,  const float* __restrict__ lnb,
    const float* __restrict__ fcw,  const float* __restrict__ fcb,
    float* __restrict__ out)
{
    __shared__ float2 s_ab[SYN_SMEM][UU];   // {a,b} for synapses SYN_REG..63 (16KB)
    __shared__ float  s_ce[SYN_SMEM][UU];   // ce for synapses SYN_REG..63 (8KB)
    __shared__ float  vsm[2][2][UU];        // v per (sub, buffer)
    __shared__ float  hbuf[2][UU];
    __shared__ float  stats[2][2];

    const int tid = threadIdx.x;
    const int sub = tid >> 6;               // 0,1 -> batch
    const int u   = tid & 63;               // unit owned
    const int b   = blockIdx.x * 2 + sub;

    // cooperative load of smem param table (SYN_SMEM*UU = 2048 entries, 16/thread)
    for (int q = tid; q < SYN_SMEM * UU; q += 128) {
        int j  = q >> 6;
        int uu = q & 63;
        float4 p = g_rparam[(SYN_REG + j) * UU + uu];
        s_ab[j][uu] = make_float2(p.x, p.y);
        s_ce[j][uu] = p.z;
    }

    float pa[SYN_REG], pb[SYN_REG], pce[SYN_REG];
#pragma unroll
    for (int j = 0; j < SYN_REG; j++) {
        float4 p = g_rparam[j * UU + u];
        pa[j] = p.x; pb[j] = p.y; pce[j] = p.z;
    }
    const float cmtu = g_cmt[u];
    const float nb   = g_numbase[u];
    const float db   = g_denbase[u];

    vsm[sub][0][u] = 0.f;
    float vu = 0.f;
    __syncthreads();

    const float2* __restrict__ wns = g_wns + (size_t)b * TT * UU;
    float2 wnd = __ldcg(&wns[u]);

    for (int t = 0; t < TT; t++) {
        float2 wnd_n = (t + 1 < TT) ? __ldcg(&wns[(t + 1) * UU + u])
                                    : make_float2(0.f, 0.f);
#pragma unroll
        for (int k = 0; k < NUNF; k++) {
            const int cur = k & 1, nxt = cur ^ 1;
            const float4* vr4 = (const float4*)vsm[sub][cur];

            float pn = 0.f, pd = 0.f;
            // register-resident synapses 0..31
#pragma unroll
            for (int q = 0; q < SYN_REG / 4; q++) {
                float4 v4 = vr4[q];
                const int s = q * 4;
                const float vv[4] = {v4.x, v4.y, v4.z, v4.w};
#pragma unroll
                for (int e = 0; e < 4; e++) {
                    float th = tanh_fast(fmaf(pa[s + e], vv[e], pb[s + e]));
                    float ce = pce[s + e];
                    pn = fmaf(ce, th, pn);
                    pd = fmaf(fabsf(ce), th, pd);
                }
            }
            // smem-resident synapses 32..63
#pragma unroll
            for (int q = 0; q < SYN_SMEM / 4; q++) {
                float4 v4 = vr4[SYN_REG / 4 + q];
                const float vv[4] = {v4.x, v4.y, v4.z, v4.w};
#pragma unroll
                for (int e = 0; e < 4; e++) {
                    float2 ab = s_ab[q * 4 + e][u];
                    float  ce = s_ce[q * 4 + e][u];
                    float th = tanh_fast(fmaf(ab.x, vv[e], ab.y));
                    pn = fmaf(ce, th, pn);
                    pd = fmaf(fabsf(ce), th, pd);
                }
            }
            float num = fmaf(cmtu, vu, nb) + wnd.x + pn;
            float den = db + wnd.y + pd;
            vu = __fdividef(num, den);
            vsm[sub][nxt][u] = vu;
            __syncthreads();
        }
        wnd = wnd_n;
    }

    // ----- head: h = v*ow + ob; LayerNorm(eps=1e-5); out = h @ fc_w^T + fc_b -----
    hbuf[sub][u] = fmaf(vu, outw[u], outb[u]);
    __syncthreads();
    {
        const int wid  = tid >> 5;
        const int lane = tid & 31;
        if ((wid & 1) == 0) {                 // warps 0 and 2 reduce sub 0 and 1
            const int s = wid >> 1;
            float h0 = hbuf[s][lane], h1 = hbuf[s][lane + 32];
            float a = h0 + h1;
            float q = h0 * h0 + h1 * h1;
#pragma unroll
            for (int o = 16; o > 0; o >>= 1) {
                a += __shfl_down_sync(0xffffffffu, a, o);
                q += __shfl_down_sync(0xffffffffu, q, o);
            }
            if (lane == 0) {
                float mean = a * (1.0f / UU);
                float var  = q * (1.0f / UU) - mean * mean;
                stats[s][0] = mean;
                stats[s][1] = rsqrtf(var + 1e-5f);
            }
            __syncwarp();
            float mean = stats[s][0], rstd = stats[s][1];
            hbuf[s][lane]      = fmaf((h0 - mean) * rstd, lnw[lane],      lnb[lane]);
            hbuf[s][lane + 32] = fmaf((h1 - mean) * rstd, lnw[lane + 32], lnb[lane + 32]);
            __syncwarp();
            if (lane < OO) {
                float acc = fcb[lane];
#pragma unroll
                for (int uu = 0; uu < UU; uu++)
                    acc = fmaf(hbuf[s][uu], fcw[lane * UU + uu], acc);
                out[(blockIdx.x * 2 + s) * OO + lane] = acc;
            }
        }
    }
}

// ---------------- launch --------------------------------------------------------------
extern "C" void kernel_launch(void* const* d_in, const int* in_sizes, int n_in,
                              void* d_out, int out_size)
{
    const float* x     = (const float*)d_in[0];
    const float* iw    = (const float*)d_in[1];
    const float* ibv   = (const float*)d_in[2];
    const float* sw    = (const float*)d_in[3];
    const float* smu   = (const float*)d_in[4];
    const float* ssig  = (const float*)d_in[5];
    const float* serev = (const float*)d_in[6];
    const float* w     = (const float*)d_in[7];
    const float* mu    = (const float*)d_in[8];
    const float* sig   = (const float*)d_in[9];
    const float* erev  = (const float*)d_in[10];
    const float* gleak = (const float*)d_in[11];
    const float* vleak = (const float*)d_in[12];
    const float* cm    = (const float*)d_in[13];
    const float* outw  = (const float*)d_in[14];
    const float* outb  = (const float*)d_in[15];
    const float* lnw   = (const float*)d_in[16];
    const float* lnb   = (const float*)d_in[17];
    const float* fcw   = (const float*)d_in[18];
    const float* fcb   = (const float*)d_in[19];
    float* out = (float*)d_out;

    const int n_syn = II * UU + UU * UU;           // 12288
    fold_params_kernel<<<(n_syn + 255) / 256, 256>>>(iw, ibv, sw, smu, ssig, serev,
                                                     w, mu, sig, erev);
    fold_neuron_kernel<<<1, 64>>>(gleak, vleak, cm);

    int nblocks = (BB * TT) / ROWS_PER_BLOCK;      // 2048
    sensory_kernel<<<nblocks, 512>>>(x);

    scan_kernel<<<BB / 2, 128>>>(outw, outb, lnw, lnb, fcw, fcb, out);
}